// round 2
// baseline (speedup 1.0000x reference)
#include <cuda_runtime.h>
#include <math.h>

// Problem constants
#define NN    20000     // nodes
#define DEG   16        // fixed in-degree (LSTM sequence length)
#define F     128       // IN == HID
#define G4    512       // 4*F gate width
#define TILE  64        // nodes per block
#define NT    256       // threads per block
#define KC4   16        // k4 (float4) per W chunk  -> 64 k floats per chunk, 2 chunks cover K=128
#define WSTRIDE 513     // float4 row stride for staged W chunk [KC4][WSTRIDE] (odd -> conflict-free)

// Scratch (allocation-free rule: __device__ globals)
__device__ float g_P [(size_t)NN * G4];   // 40.96 MB: precomputed input projections + bias
__device__ float g_H1[(size_t)NN * F];    // 10.24 MB: layer-1 output (post ReLU)

__device__ __forceinline__ float sigm(float x) { return 1.0f / (1.0f + __expf(-x)); }

// Stage W (row-major [rows][128]) chunk k = [k4base*4, k4base*4+64) into smem as
// float4 Wt4[k4][row] with row-stride WSTRIDE. Global reads coalesced (16 lanes x 16B
// contiguous per row), STS conflict-free (bank start = 4*((k4+row)%8) distinct per phase).
__device__ __forceinline__ void load_wchunk(float4* Wt4, const float* __restrict__ W,
                                            int rows, int k4base) {
    int total = rows * KC4;
    for (int idx = threadIdx.x; idx < total; idx += NT) {
        int row = idx >> 4;     // / KC4
        int k4  = idx & 15;     // % KC4
        Wt4[k4 * WSTRIDE + row] =
            *reinterpret_cast<const float4*>(W + (size_t)row * F + (size_t)(k4base + k4) * 4);
    }
}

// acc[i][g*4+uu] += sum_k Hs[node_i][k] * W[g*128 + uu*32 + ut][k] over this chunk.
// a-loads: warp-uniform broadcast LDS.128. b-loads: lanes stride-1 rows, conflict-free LDS.128.
__device__ __forceinline__ void gemm_chunk(float (&acc)[8][16],
                                           const float4* __restrict__ Wt4,
                                           const float4* __restrict__ Hs4,
                                           int nl0, int ut, int k4off) {
#pragma unroll 2
    for (int k4 = 0; k4 < KC4; ++k4) {
        float4 a[8];
#pragma unroll
        for (int i = 0; i < 8; ++i) a[i] = Hs4[(nl0 + i) * 32 + k4off + k4];
#pragma unroll
        for (int g = 0; g < 4; ++g) {
#pragma unroll
            for (int uu = 0; uu < 4; ++uu) {
                float4 b = Wt4[k4 * WSTRIDE + g * 128 + uu * 32 + ut];
                const int j = g * 4 + uu;
#pragma unroll
                for (int i = 0; i < 8; ++i) {
                    float s = acc[i][j];
                    s = fmaf(a[i].x, b.x, s);
                    s = fmaf(a[i].y, b.y, s);
                    s = fmaf(a[i].z, b.z, s);
                    s = fmaf(a[i].w, b.w, s);
                    acc[i][j] = s;
                }
            }
        }
    }
}

// ---------------------------------------------------------------------------
// proj: g_P[n][col] = sum_k X[n][k]*Wih[col][k] + bih[col] + bhh[col]
// ---------------------------------------------------------------------------
__global__ void __launch_bounds__(NT, 1)
proj_kernel(const float* __restrict__ Xin, int useH1,
            const float* __restrict__ Wih,
            const float* __restrict__ bih,
            const float* __restrict__ bhh) {
    extern __shared__ float smem[];
    float4* Hs4 = reinterpret_cast<float4*>(smem);
    float4* Wt4 = reinterpret_cast<float4*>(smem + TILE * F);

    const float* X = useH1 ? g_H1 : Xin;
    const int tid = threadIdx.x, ut = tid & 31, nt = tid >> 5;
    const int tile0 = blockIdx.x * TILE;
    const int nl0 = nt * 8;

    // Stage X tile into smem (coalesced float4)
    for (int idx = tid; idx < TILE * 32; idx += NT) {
        int r = idx >> 5, c4 = idx & 31;
        int n = tile0 + r;
        float4 v = make_float4(0.f, 0.f, 0.f, 0.f);
        if (n < NN) v = *reinterpret_cast<const float4*>(X + (size_t)n * F + c4 * 4);
        Hs4[idx] = v;
    }

    float acc[8][16];
#pragma unroll
    for (int g = 0; g < 4; ++g)
#pragma unroll
        for (int uu = 0; uu < 4; ++uu) {
            int col = g * 128 + uu * 32 + ut;
            float b0 = __ldg(bih + col) + __ldg(bhh + col);
#pragma unroll
            for (int i = 0; i < 8; ++i) acc[i][g * 4 + uu] = b0;
        }

#pragma unroll 1
    for (int c2 = 0; c2 < 2; ++c2) {
        __syncthreads();
        load_wchunk(Wt4, Wih, G4, c2 * KC4);
        __syncthreads();
        gemm_chunk(acc, Wt4, Hs4, nl0, ut, c2 * KC4);
    }

#pragma unroll
    for (int i = 0; i < 8; ++i) {
        int n = tile0 + nl0 + i;
        if (n < NN) {
#pragma unroll
            for (int g = 0; g < 4; ++g)
#pragma unroll
                for (int uu = 0; uu < 4; ++uu)
                    g_P[(size_t)n * G4 + g * 128 + uu * 32 + ut] = acc[i][g * 4 + uu];
        }
    }
}

// ---------------------------------------------------------------------------
// rec: 16-step LSTM recurrence on gathered projections + layer epilogue.
// LAYER==1: writes g_H1 = relu(x@Wself.T + hN@Wneigh.T + bneigh)
// LAYER==2: writes out[n] = sigmoid(h1[n].Wself + hN[n].Wneigh + b)
// ---------------------------------------------------------------------------
template <int LAYER>
__global__ void __launch_bounds__(NT, 1)
rec_kernel(const float* __restrict__ Xin,
           const int* __restrict__ nbr,
           const float* __restrict__ Whh,
           const float* __restrict__ Wself,
           const float* __restrict__ Wneigh,
           const float* __restrict__ bneigh,
           float* __restrict__ out) {
    extern __shared__ float smem[];
    float*  Hs  = smem;                                       // [64][128] h state
    float4* Hs4 = reinterpret_cast<float4*>(smem);
    float4* Wt4 = reinterpret_cast<float4*>(smem + TILE * F);

    const float* X = (LAYER == 1) ? Xin : g_H1;
    const int tid = threadIdx.x, ut = tid & 31, nt = tid >> 5;
    const int tile0 = blockIdx.x * TILE;
    const int nl0 = nt * 8;

    float c[8][4];
#pragma unroll
    for (int i = 0; i < 8; ++i)
#pragma unroll
        for (int uu = 0; uu < 4; ++uu) c[i][uu] = 0.0f;

#pragma unroll 1
    for (int t = 0; t < DEG; ++t) {
        float acc[8][16];
        // Gather: acc init = P[nbr[n][t]][gate cols]. Coalesced 128B per (node,gate,uu).
#pragma unroll
        for (int i = 0; i < 8; ++i) {
            int n = tile0 + nl0 + i;
            int jn = (n < NN) ? __ldg(nbr + (size_t)n * DEG + t) : 0;
            const float* Pr = g_P + (size_t)jn * G4;
#pragma unroll
            for (int g = 0; g < 4; ++g)
#pragma unroll
                for (int uu = 0; uu < 4; ++uu)
                    acc[i][g * 4 + uu] = __ldg(Pr + g * 128 + uu * 32 + ut);
        }
        // Recurrent GEMM: gates += h @ Whh.T   (skip at t=0, h==0)
        if (t > 0) {
#pragma unroll 1
            for (int c2 = 0; c2 < 2; ++c2) {
                __syncthreads();
                load_wchunk(Wt4, Whh, G4, c2 * KC4);
                __syncthreads();
                gemm_chunk(acc, Wt4, Hs4, nl0, ut, c2 * KC4);
            }
        }
        // Elementwise LSTM cell (gate order i,f,g,o)
#pragma unroll
        for (int i = 0; i < 8; ++i)
#pragma unroll
            for (int uu = 0; uu < 4; ++uu) {
                float ig = sigm(acc[i][0 + uu]);
                float fg = sigm(acc[i][4 + uu]);
                float gg = tanhf(acc[i][8 + uu]);
                float og = sigm(acc[i][12 + uu]);
                float cc = fmaf(fg, c[i][uu], ig * gg);
                c[i][uu] = cc;
                Hs[(nl0 + i) * F + uu * 32 + ut] = og * tanhf(cc);
            }
        __syncwarp();  // H rows are warp-private; next reads ordered by chunk syncthreads
    }

    if (LAYER == 1) {
        float oacc[8][4];
#pragma unroll
        for (int uu = 0; uu < 4; ++uu) {
            float b0 = __ldg(bneigh + uu * 32 + ut);
#pragma unroll
            for (int i = 0; i < 8; ++i) oacc[i][uu] = b0;
        }
        // self term: X rows from global
#pragma unroll 1
        for (int c2 = 0; c2 < 2; ++c2) {
            __syncthreads();
            load_wchunk(Wt4, Wself, F, c2 * KC4);
            __syncthreads();
#pragma unroll 2
            for (int k4 = 0; k4 < KC4; ++k4) {
                float4 a[8];
#pragma unroll
                for (int i = 0; i < 8; ++i) {
                    int n = tile0 + nl0 + i;
                    a[i] = (n < NN)
                         ? *reinterpret_cast<const float4*>(X + (size_t)n * F + (c2 * KC4 + k4) * 4)
                         : make_float4(0.f, 0.f, 0.f, 0.f);
                }
#pragma unroll
                for (int uu = 0; uu < 4; ++uu) {
                    float4 b = Wt4[k4 * WSTRIDE + uu * 32 + ut];
#pragma unroll
                    for (int i = 0; i < 8; ++i)
                        oacc[i][uu] = fmaf(a[i].x, b.x, fmaf(a[i].y, b.y,
                                      fmaf(a[i].z, b.z, fmaf(a[i].w, b.w, oacc[i][uu]))));
                }
            }
        }
        // neighbor term: final h from smem
#pragma unroll 1
        for (int c2 = 0; c2 < 2; ++c2) {
            __syncthreads();
            load_wchunk(Wt4, Wneigh, F, c2 * KC4);
            __syncthreads();
#pragma unroll 2
            for (int k4 = 0; k4 < KC4; ++k4) {
                float4 a[8];
#pragma unroll
                for (int i = 0; i < 8; ++i) a[i] = Hs4[(nl0 + i) * 32 + c2 * KC4 + k4];
#pragma unroll
                for (int uu = 0; uu < 4; ++uu) {
                    float4 b = Wt4[k4 * WSTRIDE + uu * 32 + ut];
#pragma unroll
                    for (int i = 0; i < 8; ++i)
                        oacc[i][uu] = fmaf(a[i].x, b.x, fmaf(a[i].y, b.y,
                                      fmaf(a[i].z, b.z, fmaf(a[i].w, b.w, oacc[i][uu]))));
                }
            }
        }
#pragma unroll
        for (int i = 0; i < 8; ++i) {
            int n = tile0 + nl0 + i;
            if (n < NN) {
#pragma unroll
                for (int uu = 0; uu < 4; ++uu)
                    g_H1[(size_t)n * F + uu * 32 + ut] = fmaxf(oacc[i][uu], 0.0f);
            }
        }
    } else {
        // OUT=1 epilogue: per-node dot products, warp butterfly reduce
        float part[8];
#pragma unroll
        for (int i = 0; i < 8; ++i) part[i] = 0.0f;
#pragma unroll
        for (int uu = 0; uu < 4; ++uu) {
            int u = uu * 32 + ut;
            float wn = __ldg(Wneigh + u);
            float ws = __ldg(Wself + u);
#pragma unroll
            for (int i = 0; i < 8; ++i) {
                int n = tile0 + nl0 + i;
                float hx = Hs[(nl0 + i) * F + u];
                float xx = (n < NN) ? __ldg(X + (size_t)n * F + u) : 0.0f;
                part[i] = fmaf(hx, wn, fmaf(xx, ws, part[i]));
            }
        }
        float b0 = __ldg(bneigh);
#pragma unroll
        for (int off = 16; off > 0; off >>= 1)
#pragma unroll
            for (int i = 0; i < 8; ++i)
                part[i] += __shfl_xor_sync(0xffffffffu, part[i], off);
        if (ut == 0) {
#pragma unroll
            for (int i = 0; i < 8; ++i) {
                int n = tile0 + nl0 + i;
                if (n < NN) out[n] = sigm(part[i] + b0);
            }
        }
    }
}

extern "C" void kernel_launch(void* const* d_in, const int* in_sizes, int n_in,
                              void* d_out, int out_size) {
    const float* x       = (const float*)d_in[0];
    const int*   nbr     = (const int*)  d_in[1];
    const float* Wih1    = (const float*)d_in[2];
    const float* Whh1    = (const float*)d_in[3];
    const float* bih1    = (const float*)d_in[4];
    const float* bhh1    = (const float*)d_in[5];
    const float* Wself1  = (const float*)d_in[6];
    const float* Wneigh1 = (const float*)d_in[7];
    const float* bneigh1 = (const float*)d_in[8];
    const float* Wih2    = (const float*)d_in[9];
    const float* Whh2    = (const float*)d_in[10];
    const float* bih2    = (const float*)d_in[11];
    const float* bhh2    = (const float*)d_in[12];
    const float* Wself2  = (const float*)d_in[13];
    const float* Wneigh2 = (const float*)d_in[14];
    const float* bneigh2 = (const float*)d_in[15];
    float* out = (float*)d_out;

    const int    nb   = (NN + TILE - 1) / TILE;          // 313 blocks
    const size_t smem = (size_t)TILE * F * 4 + (size_t)KC4 * WSTRIDE * 16;  // 164,096 B

    cudaFuncSetAttribute(proj_kernel,   cudaFuncAttributeMaxDynamicSharedMemorySize, (int)smem);
    cudaFuncSetAttribute(rec_kernel<1>, cudaFuncAttributeMaxDynamicSharedMemorySize, (int)smem);
    cudaFuncSetAttribute(rec_kernel<2>, cudaFuncAttributeMaxDynamicSharedMemorySize, (int)smem);

    // Layer 1
    proj_kernel<<<nb, NT, smem>>>(x, 0, Wih1, bih1, bhh1);
    rec_kernel<1><<<nb, NT, smem>>>(x, nbr, Whh1, Wself1, Wneigh1, bneigh1, nullptr);
    // Layer 2
    proj_kernel<<<nb, NT, smem>>>(nullptr, 1, Wih2, bih2, bhh2);
    rec_kernel<2><<<nb, NT, smem>>>(nullptr, nbr, Whh2, Wself2, Wneigh2, bneigh2, out);
}

// round 3
// speedup vs baseline: 1.0009x; 1.0009x over previous
#include <cuda_runtime.h>
#include <math.h>

// Problem constants
#define NN    20000     // nodes
#define DEG   16        // fixed in-degree (LSTM sequence length)
#define F     128       // IN == HID
#define G4    512       // 4*F gate width
#define TILE  64        // nodes per block
#define NT    256       // threads per block
#define KC4   16        // k4 (float4) per W chunk  -> 64 k floats per chunk, 2 chunks cover K=128
#define WSTRIDE 513     // float4 row stride for staged W chunk [KC4][WSTRIDE] (odd -> conflict-free)

// Scratch (allocation-free rule: __device__ globals)
__device__ float g_P [(size_t)NN * G4];   // 40.96 MB: precomputed input projections + bias
__device__ float g_H1[(size_t)NN * F];    // 10.24 MB: layer-1 output (post ReLU)

__device__ __forceinline__ float sigm(float x) { return 1.0f / (1.0f + __expf(-x)); }

// Stage W (row-major [rows][128]) chunk k = [k4base*4, k4base*4+64) into smem as
// float4 Wt4[k4][row] with row-stride WSTRIDE. Global reads coalesced (16 lanes x 16B
// contiguous per row), STS conflict-free (bank start = 4*((k4+row)%8) distinct per phase).
__device__ __forceinline__ void load_wchunk(float4* Wt4, const float* __restrict__ W,
                                            int rows, int k4base) {
    int total = rows * KC4;
    for (int idx = threadIdx.x; idx < total; idx += NT) {
        int row = idx >> 4;     // / KC4
        int k4  = idx & 15;     // % KC4
        Wt4[k4 * WSTRIDE + row] =
            *reinterpret_cast<const float4*>(W + (size_t)row * F + (size_t)(k4base + k4) * 4);
    }
}

// acc[i][g*4+uu] += sum_k Hs[node_i][k] * W[g*128 + uu*32 + ut][k] over this chunk.
// a-loads: warp-uniform broadcast LDS.128. b-loads: lanes stride-1 rows, conflict-free LDS.128.
__device__ __forceinline__ void gemm_chunk(float (&acc)[8][16],
                                           const float4* __restrict__ Wt4,
                                           const float4* __restrict__ Hs4,
                                           int nl0, int ut, int k4off) {
#pragma unroll 2
    for (int k4 = 0; k4 < KC4; ++k4) {
        float4 a[8];
#pragma unroll
        for (int i = 0; i < 8; ++i) a[i] = Hs4[(nl0 + i) * 32 + k4off + k4];
#pragma unroll
        for (int g = 0; g < 4; ++g) {
#pragma unroll
            for (int uu = 0; uu < 4; ++uu) {
                float4 b = Wt4[k4 * WSTRIDE + g * 128 + uu * 32 + ut];
                const int j = g * 4 + uu;
#pragma unroll
                for (int i = 0; i < 8; ++i) {
                    float s = acc[i][j];
                    s = fmaf(a[i].x, b.x, s);
                    s = fmaf(a[i].y, b.y, s);
                    s = fmaf(a[i].z, b.z, s);
                    s = fmaf(a[i].w, b.w, s);
                    acc[i][j] = s;
                }
            }
        }
    }
}

// ---------------------------------------------------------------------------
// proj: g_P[n][col] = sum_k X[n][k]*Wih[col][k] + bih[col] + bhh[col]
// ---------------------------------------------------------------------------
__global__ void __launch_bounds__(NT, 1)
proj_kernel(const float* __restrict__ Xin, int useH1,
            const float* __restrict__ Wih,
            const float* __restrict__ bih,
            const float* __restrict__ bhh) {
    extern __shared__ float smem[];
    float4* Hs4 = reinterpret_cast<float4*>(smem);
    float4* Wt4 = reinterpret_cast<float4*>(smem + TILE * F);

    const float* X = useH1 ? g_H1 : Xin;
    const int tid = threadIdx.x, ut = tid & 31, nt = tid >> 5;
    const int tile0 = blockIdx.x * TILE;
    const int nl0 = nt * 8;

    // Stage X tile into smem (coalesced float4)
    for (int idx = tid; idx < TILE * 32; idx += NT) {
        int r = idx >> 5, c4 = idx & 31;
        int n = tile0 + r;
        float4 v = make_float4(0.f, 0.f, 0.f, 0.f);
        if (n < NN) v = *reinterpret_cast<const float4*>(X + (size_t)n * F + c4 * 4);
        Hs4[idx] = v;
    }

    float acc[8][16];
#pragma unroll
    for (int g = 0; g < 4; ++g)
#pragma unroll
        for (int uu = 0; uu < 4; ++uu) {
            int col = g * 128 + uu * 32 + ut;
            float b0 = __ldg(bih + col) + __ldg(bhh + col);
#pragma unroll
            for (int i = 0; i < 8; ++i) acc[i][g * 4 + uu] = b0;
        }

#pragma unroll 1
    for (int c2 = 0; c2 < 2; ++c2) {
        __syncthreads();
        load_wchunk(Wt4, Wih, G4, c2 * KC4);
        __syncthreads();
        gemm_chunk(acc, Wt4, Hs4, nl0, ut, c2 * KC4);
    }

#pragma unroll
    for (int i = 0; i < 8; ++i) {
        int n = tile0 + nl0 + i;
        if (n < NN) {
#pragma unroll
            for (int g = 0; g < 4; ++g)
#pragma unroll
                for (int uu = 0; uu < 4; ++uu)
                    g_P[(size_t)n * G4 + g * 128 + uu * 32 + ut] = acc[i][g * 4 + uu];
        }
    }
}

// ---------------------------------------------------------------------------
// rec: 16-step LSTM recurrence on gathered projections + layer epilogue.
// LAYER==1: writes g_H1 = relu(x@Wself.T + hN@Wneigh.T + bneigh)
// LAYER==2: writes out[n] = sigmoid(h1[n].Wself + hN[n].Wneigh + b)
// ---------------------------------------------------------------------------
template <int LAYER>
__global__ void __launch_bounds__(NT, 1)
rec_kernel(const float* __restrict__ Xin,
           const int* __restrict__ nbr,
           const float* __restrict__ Whh,
           const float* __restrict__ Wself,
           const float* __restrict__ Wneigh,
           const float* __restrict__ bneigh,
           float* __restrict__ out) {
    extern __shared__ float smem[];
    float*  Hs  = smem;                                       // [64][128] h state
    float4* Hs4 = reinterpret_cast<float4*>(smem);
    float4* Wt4 = reinterpret_cast<float4*>(smem + TILE * F);

    const float* X = (LAYER == 1) ? Xin : g_H1;
    const int tid = threadIdx.x, ut = tid & 31, nt = tid >> 5;
    const int tile0 = blockIdx.x * TILE;
    const int nl0 = nt * 8;

    float c[8][4];
#pragma unroll
    for (int i = 0; i < 8; ++i)
#pragma unroll
        for (int uu = 0; uu < 4; ++uu) c[i][uu] = 0.0f;

#pragma unroll 1
    for (int t = 0; t < DEG; ++t) {
        float acc[8][16];
        // Gather: acc init = P[nbr[n][t]][gate cols]. Coalesced 128B per (node,gate,uu).
#pragma unroll
        for (int i = 0; i < 8; ++i) {
            int n = tile0 + nl0 + i;
            int jn = (n < NN) ? __ldg(nbr + (size_t)n * DEG + t) : 0;
            const float* Pr = g_P + (size_t)jn * G4;
#pragma unroll
            for (int g = 0; g < 4; ++g)
#pragma unroll
                for (int uu = 0; uu < 4; ++uu)
                    acc[i][g * 4 + uu] = __ldg(Pr + g * 128 + uu * 32 + ut);
        }
        // Recurrent GEMM: gates += h @ Whh.T   (skip at t=0, h==0)
        if (t > 0) {
#pragma unroll 1
            for (int c2 = 0; c2 < 2; ++c2) {
                __syncthreads();
                load_wchunk(Wt4, Whh, G4, c2 * KC4);
                __syncthreads();
                gemm_chunk(acc, Wt4, Hs4, nl0, ut, c2 * KC4);
            }
        }
        // Elementwise LSTM cell (gate order i,f,g,o)
#pragma unroll
        for (int i = 0; i < 8; ++i)
#pragma unroll
            for (int uu = 0; uu < 4; ++uu) {
                float ig = sigm(acc[i][0 + uu]);
                float fg = sigm(acc[i][4 + uu]);
                float gg = tanhf(acc[i][8 + uu]);
                float og = sigm(acc[i][12 + uu]);
                float cc = fmaf(fg, c[i][uu], ig * gg);
                c[i][uu] = cc;
                Hs[(nl0 + i) * F + uu * 32 + ut] = og * tanhf(cc);
            }
        __syncwarp();  // H rows are warp-private; next reads ordered by chunk syncthreads
    }

    if (LAYER == 1) {
        float oacc[8][4];
#pragma unroll
        for (int uu = 0; uu < 4; ++uu) {
            float b0 = __ldg(bneigh + uu * 32 + ut);
#pragma unroll
            for (int i = 0; i < 8; ++i) oacc[i][uu] = b0;
        }
        // self term: X rows from global
#pragma unroll 1
        for (int c2 = 0; c2 < 2; ++c2) {
            __syncthreads();
            load_wchunk(Wt4, Wself, F, c2 * KC4);
            __syncthreads();
#pragma unroll 2
            for (int k4 = 0; k4 < KC4; ++k4) {
                float4 a[8];
#pragma unroll
                for (int i = 0; i < 8; ++i) {
                    int n = tile0 + nl0 + i;
                    a[i] = (n < NN)
                         ? *reinterpret_cast<const float4*>(X + (size_t)n * F + (c2 * KC4 + k4) * 4)
                         : make_float4(0.f, 0.f, 0.f, 0.f);
                }
#pragma unroll
                for (int uu = 0; uu < 4; ++uu) {
                    float4 b = Wt4[k4 * WSTRIDE + uu * 32 + ut];
#pragma unroll
                    for (int i = 0; i < 8; ++i)
                        oacc[i][uu] = fmaf(a[i].x, b.x, fmaf(a[i].y, b.y,
                                      fmaf(a[i].z, b.z, fmaf(a[i].w, b.w, oacc[i][uu]))));
                }
            }
        }
        // neighbor term: final h from smem
#pragma unroll 1
        for (int c2 = 0; c2 < 2; ++c2) {
            __syncthreads();
            load_wchunk(Wt4, Wneigh, F, c2 * KC4);
            __syncthreads();
#pragma unroll 2
            for (int k4 = 0; k4 < KC4; ++k4) {
                float4 a[8];
#pragma unroll
                for (int i = 0; i < 8; ++i) a[i] = Hs4[(nl0 + i) * 32 + c2 * KC4 + k4];
#pragma unroll
                for (int uu = 0; uu < 4; ++uu) {
                    float4 b = Wt4[k4 * WSTRIDE + uu * 32 + ut];
#pragma unroll
                    for (int i = 0; i < 8; ++i)
                        oacc[i][uu] = fmaf(a[i].x, b.x, fmaf(a[i].y, b.y,
                                      fmaf(a[i].z, b.z, fmaf(a[i].w, b.w, oacc[i][uu]))));
                }
            }
        }
#pragma unroll
        for (int i = 0; i < 8; ++i) {
            int n = tile0 + nl0 + i;
            if (n < NN) {
#pragma unroll
                for (int uu = 0; uu < 4; ++uu)
                    g_H1[(size_t)n * F + uu * 32 + ut] = fmaxf(oacc[i][uu], 0.0f);
            }
        }
    } else {
        // OUT=1 epilogue: per-node dot products, warp butterfly reduce
        float part[8];
#pragma unroll
        for (int i = 0; i < 8; ++i) part[i] = 0.0f;
#pragma unroll
        for (int uu = 0; uu < 4; ++uu) {
            int u = uu * 32 + ut;
            float wn = __ldg(Wneigh + u);
            float ws = __ldg(Wself + u);
#pragma unroll
            for (int i = 0; i < 8; ++i) {
                int n = tile0 + nl0 + i;
                float hx = Hs[(nl0 + i) * F + u];
                float xx = (n < NN) ? __ldg(X + (size_t)n * F + u) : 0.0f;
                part[i] = fmaf(hx, wn, fmaf(xx, ws, part[i]));
            }
        }
        float b0 = __ldg(bneigh);
#pragma unroll
        for (int off = 16; off > 0; off >>= 1)
#pragma unroll
            for (int i = 0; i < 8; ++i)
                part[i] += __shfl_xor_sync(0xffffffffu, part[i], off);
        if (ut == 0) {
#pragma unroll
            for (int i = 0; i < 8; ++i) {
                int n = tile0 + nl0 + i;
                if (n < NN) out[n] = sigm(part[i] + b0);
            }
        }
    }
}

extern "C" void kernel_launch(void* const* d_in, const int* in_sizes, int n_in,
                              void* d_out, int out_size) {
    const float* x       = (const float*)d_in[0];
    const int*   nbr     = (const int*)  d_in[1];
    const float* Wih1    = (const float*)d_in[2];
    const float* Whh1    = (const float*)d_in[3];
    const float* bih1    = (const float*)d_in[4];
    const float* bhh1    = (const float*)d_in[5];
    const float* Wself1  = (const float*)d_in[6];
    const float* Wneigh1 = (const float*)d_in[7];
    const float* bneigh1 = (const float*)d_in[8];
    const float* Wih2    = (const float*)d_in[9];
    const float* Whh2    = (const float*)d_in[10];
    const float* bih2    = (const float*)d_in[11];
    const float* bhh2    = (const float*)d_in[12];
    const float* Wself2  = (const float*)d_in[13];
    const float* Wneigh2 = (const float*)d_in[14];
    const float* bneigh2 = (const float*)d_in[15];
    float* out = (float*)d_out;

    const int    nb   = (NN + TILE - 1) / TILE;          // 313 blocks
    const size_t smem = (size_t)TILE * F * 4 + (size_t)KC4 * WSTRIDE * 16;  // 164,096 B

    cudaFuncSetAttribute(proj_kernel,   cudaFuncAttributeMaxDynamicSharedMemorySize, (int)smem);
    cudaFuncSetAttribute(rec_kernel<1>, cudaFuncAttributeMaxDynamicSharedMemorySize, (int)smem);
    cudaFuncSetAttribute(rec_kernel<2>, cudaFuncAttributeMaxDynamicSharedMemorySize, (int)smem);

    // Layer 1
    proj_kernel<<<nb, NT, smem>>>(x, 0, Wih1, bih1, bhh1);
    rec_kernel<1><<<nb, NT, smem>>>(x, nbr, Whh1, Wself1, Wneigh1, bneigh1, nullptr);
    // Layer 2
    proj_kernel<<<nb, NT, smem>>>(nullptr, 1, Wih2, bih2, bhh2);
    rec_kernel<2><<<nb, NT, smem>>>(nullptr, nbr, Whh2, Wself2, Wneigh2, bneigh2, out);
}